// round 2
// baseline (speedup 1.0000x reference)
#include <cuda_runtime.h>
#include <stdint.h>

// ---------------- problem constants ----------------
#define NC    80
#define A0    4096
#define A1    1024
#define A2    256
#define N0    (A0*NC)          // 327680
#define N1    (A1*NC)          // 81920
#define N2    (A2*NC)          // 20480
#define TOT   (N0+N1+N2)       // 430080 per image
#define OFF1  N0
#define OFF2  (N0+N1)
#define NB    8
#define TOPK  1000
#define NLVL  3
#define NPAIR (NB*NLVL)        // 24
#define CAND  3000
#define DETS  100
#define IMGSZ 2048.0f
#define NMS_T 0.6f
#define CAP   4096             // collect capacity per (image,level)
#define SHB   2048             // shared box capacity in NMS

// ---------------- scratch (device globals; no allocations) ----------------
__device__ uint32_t g_keys[NB*TOT];                 // ~13.8 MB
__device__ uint32_t g_hist[NPAIR*256];
__device__ uint32_t g_prefix[NPAIR];
__device__ uint32_t g_krem[NPAIR];
__device__ uint32_t g_ccnt[NPAIR];
__device__ unsigned long long g_cand[NPAIR*CAP];
__device__ float    g_score[NB*CAND];
__device__ int      g_labelv[NB*CAND];
__device__ float    g_boxv[NB*CAND*4];
__device__ int      g_rank2pos[NB*CAND];
__device__ float    g_ss[NB*CAND];
__device__ int      g_clsrank[NB*CAND];
__device__ int      g_segstart[NB*NC];
__device__ int      g_segcnt[NB*NC];
__device__ unsigned char g_keep[NB*CAND];

// ---------------- helpers ----------------
__device__ __forceinline__ uint32_t f2k(float f){
    uint32_t u = __float_as_uint(f);
    return (u & 0x80000000u) ? ~u : (u | 0x80000000u);
}
__device__ __forceinline__ float k2f(uint32_t k){
    uint32_t u = (k & 0x80000000u) ? (k ^ 0x80000000u) : ~k;
    return __uint_as_float(u);
}
// XLA expands logistic(x) -> 0.5 + 0.5*tanh(0.5*x); 0.5*t is exact so FMA is identical.
__device__ __forceinline__ float sigm(float x){
    return 0.5f*tanhf(0.5f*x) + 0.5f;
}

// block-wide bitonic sort of 4096 elements, blockDim.x == 1024, ascending
template<typename T>
__device__ __forceinline__ void bitonic4096(T* s){
    const int tid = threadIdx.x;
    for (int k = 2; k <= 4096; k <<= 1){
        for (int j = k >> 1; j > 0; j >>= 1){
            __syncthreads();
            #pragma unroll
            for (int w = 0; w < 4; ++w){
                int i   = tid + w*1024;
                int ixj = i ^ j;
                if (ixj > i){
                    T a = s[i], b = s[ixj];
                    bool up = ((i & k) == 0);
                    if ((a > b) == up){ s[i] = b; s[ixj] = a; }
                }
            }
        }
    }
    __syncthreads();
}

// ---------------- kernels ----------------
__global__ void k_init(){
    int t = blockIdx.x*blockDim.x + threadIdx.x;
    if (t < NPAIR){ g_prefix[t] = 0; g_krem[t] = TOPK; g_ccnt[t] = 0; }
    for (int i = t; i < NPAIR*256; i += gridDim.x*blockDim.x) g_hist[i] = 0;
}

// scores -> sort keys, plus round-0 (top byte) histogram, fused
__global__ __launch_bounds__(256) void k_scores(
    const float* __restrict__ cls0, const float* __restrict__ cls1, const float* __restrict__ cls2,
    const float* __restrict__ ctr0, const float* __restrict__ ctr1, const float* __restrict__ ctr2)
{
    __shared__ uint32_t h[NLVL*256];
    const int tid = threadIdx.x;
    for (int t = tid; t < NLVL*256; t += blockDim.x) h[t] = 0;
    __syncthreads();

    const int b = blockIdx.y;
    const int i = blockIdx.x*blockDim.x + tid;
    if (i < TOT){
        int l, j, A; const float* cls; const float* ctr;
        if (i < OFF1){ l = 0; j = i;        cls = cls0; ctr = ctr0; A = A0; }
        else if (i < OFF2){ l = 1; j = i - OFF1; cls = cls1; ctr = ctr1; A = A1; }
        else { l = 2; j = i - OFF2; cls = cls2; ctr = ctr2; A = A2; }
        float c = cls[(size_t)b*((size_t)A*NC) + j];
        float t = ctr[(size_t)b*A + j/NC];
        float sa = sigm(c);
        float st = sigm(t);
        float s  = sqrtf(__fmul_rn(sa, st));
        uint32_t key = (s > 0.2f) ? f2k(s) : 0x407FFFFFu;  // f2k(-1.0f)
        g_keys[(size_t)b*TOT + i] = key;
        atomicAdd(&h[l*256 + (key >> 24)], 1u);
    }
    __syncthreads();
    for (int t = tid; t < NLVL*256; t += blockDim.x){
        uint32_t v = h[t];
        if (v) atomicAdd(&g_hist[(b*NLVL + t/256)*256 + (t & 255)], v);
    }
}

// histogram of byte at 'shift' among keys matching current prefix (bytes above shift)
__global__ __launch_bounds__(256) void k_hist(int shift){
    __shared__ uint32_t h[NLVL*256];
    const int tid = threadIdx.x;
    for (int t = tid; t < NLVL*256; t += blockDim.x) h[t] = 0;
    __syncthreads();

    const int b = blockIdx.y;
    const int i = blockIdx.x*blockDim.x + tid;
    if (i < TOT){
        int l = (i < OFF1) ? 0 : (i < OFF2) ? 1 : 2;
        uint32_t key    = g_keys[(size_t)b*TOT + i];
        uint32_t prefix = g_prefix[b*NLVL + l];
        if (((key ^ prefix) >> (shift + 8)) == 0)
            atomicAdd(&h[l*256 + ((key >> shift) & 255u)], 1u);
    }
    __syncthreads();
    for (int t = tid; t < NLVL*256; t += blockDim.x){
        uint32_t v = h[t];
        if (v) atomicAdd(&g_hist[(b*NLVL + t/256)*256 + (t & 255)], v);
    }
}

// pick pivot byte per (image,level); zero histogram for next round
__global__ void k_pivot(int shift){
    int t = threadIdx.x;
    if (t < NPAIR){
        uint32_t krem = g_krem[t];
        uint32_t cum  = 0;
        int      sel  = -1;
        uint32_t krn  = krem;
        for (int v = 255; v >= 0; --v){
            uint32_t c = g_hist[t*256 + v];
            g_hist[t*256 + v] = 0;
            if (sel < 0){
                if (cum + c >= krem){ sel = v; krn = krem - cum; }
                cum += c;
            }
        }
        if (sel < 0){ sel = 0; }
        g_prefix[t] = g_prefix[t] | ((uint32_t)sel << shift);
        g_krem[t]   = krn;
    }
}

// collect all keys >= pivot into (~key<<32 | level-local-idx) composites
__global__ __launch_bounds__(256) void k_collect(){
    const int b = blockIdx.y;
    const int i = blockIdx.x*blockDim.x + threadIdx.x;
    if (i >= TOT) return;
    int l, j;
    if (i < OFF1){ l = 0; j = i; }
    else if (i < OFF2){ l = 1; j = i - OFF1; }
    else { l = 2; j = i - OFF2; }
    const int pair = b*NLVL + l;
    uint32_t key = g_keys[(size_t)b*TOT + i];
    uint32_t P   = g_prefix[pair];
    if (key >= P){
        uint32_t slot = atomicAdd(&g_ccnt[pair], 1u);
        if (slot < CAP)
            g_cand[pair*CAP + slot] =
                ((unsigned long long)(~key) << 32) | (unsigned long long)(uint32_t)j;
    }
}

// per (image,level): sort candidates (score desc, idx asc), emit top-1000, decode boxes
__global__ __launch_bounds__(1024) void k_sortlevel(
    const float* __restrict__ reg0, const float* __restrict__ reg1, const float* __restrict__ reg2,
    const float* __restrict__ anc0, const float* __restrict__ anc1, const float* __restrict__ anc2)
{
    __shared__ unsigned long long s[4096];
    const int p = blockIdx.x, b = p/NLVL, l = p%NLVL;
    const int tid = threadIdx.x;
    uint32_t cnt = g_ccnt[p]; if (cnt > CAP) cnt = CAP;
    for (int i = tid; i < 4096; i += 1024)
        s[i] = (i < (int)cnt) ? g_cand[p*CAP + i] : 0xFFFFFFFFFFFFFFFFULL;
    bitonic4096(s);

    if (tid < TOPK){
        unsigned long long cc = s[tid];
        float sc = -1.0f; int aidx = 0, lab = 0;
        if (tid < (int)cnt){
            uint32_t key = ~(uint32_t)(cc >> 32);
            uint32_t idx = (uint32_t)cc;
            sc   = k2f(key);
            aidx = (int)(idx / NC);
            lab  = (int)(idx % NC);
        }
        const int pos = b*CAND + l*TOPK + tid;
        g_score[pos]  = sc;
        g_labelv[pos] = lab;

        const float* reg; const float* anc; int A;
        if (l == 0){ reg = reg0; anc = anc0; A = A0; }
        else if (l == 1){ reg = reg1; anc = anc1; A = A1; }
        else { reg = reg2; anc = anc2; A = A2; }
        const float* a = anc + (size_t)aidx*4;
        const float* r = reg + ((size_t)b*A + aidx)*4;
        float a0 = a[0], a1 = a[1], a2 = a[2], a3 = a[3];
        float cx = __fmul_rn(0.5f, __fadd_rn(a0, a2));
        float cy = __fmul_rn(0.5f, __fadd_rn(a1, a3));
        float w  = __fsub_rn(a2, a0);
        float h  = __fsub_rn(a3, a1);
        float x1 = __fsub_rn(cx, __fmul_rn(r[0], w));
        float y1 = __fsub_rn(cy, __fmul_rn(r[1], h));
        float x2 = __fadd_rn(cx, __fmul_rn(r[2], w));
        float y2 = __fadd_rn(cy, __fmul_rn(r[3], h));
        x1 = fminf(fmaxf(x1, 0.0f), IMGSZ);
        y1 = fminf(fmaxf(y1, 0.0f), IMGSZ);
        x2 = fminf(fmaxf(x2, 0.0f), IMGSZ);
        y2 = fminf(fmaxf(y2, 0.0f), IMGSZ);
        g_boxv[pos*4+0] = x1; g_boxv[pos*4+1] = y1;
        g_boxv[pos*4+2] = x2; g_boxv[pos*4+3] = y2;
    }
}

// per image: global stable sort by score, then class-group sort, segment table
__global__ __launch_bounds__(1024) void k_sortimage(){
    __shared__ unsigned long long s[4096];
    __shared__ int firstc[NC];
    const int b = blockIdx.x, tid = threadIdx.x;

    for (int i = tid; i < 4096; i += 1024){
        if (i < CAND){
            float sc = g_score[b*CAND + i];
            s[i] = ((unsigned long long)(~f2k(sc)) << 32) | (unsigned long long)(uint32_t)i;
        } else s[i] = 0xFFFFFFFFFFFFFFFFULL;
    }
    bitonic4096(s);
    for (int r = tid; r < CAND; r += 1024){
        int pos = (int)(uint32_t)s[r];
        g_rank2pos[b*CAND + r] = pos;
        g_ss[b*CAND + r]       = g_score[b*CAND + pos];
    }
    if (tid < NC) firstc[tid] = 0x7FFFFFFF;
    __syncthreads();   // rank2pos visible block-wide; s free for reuse

    uint32_t* s32 = (uint32_t*)s;
    for (int i = tid; i < 4096; i += 1024){
        uint32_t v = 0xFFFFFFFFu;
        if (i < CAND){
            int pos = g_rank2pos[b*CAND + i];
            int lab = g_labelv[b*CAND + pos];
            v = ((uint32_t)lab << 12) | (uint32_t)i;   // (class, rank) ascending
        }
        s32[i] = v;
    }
    bitonic4096(s32);
    for (int j = tid; j < CAND; j += 1024){
        uint32_t v = s32[j];
        int r = (int)(v & 4095u);
        g_clsrank[b*CAND + j] = r;
        int c = (int)(v >> 12);
        atomicMin(&firstc[c], j);
    }
    __syncthreads();
    if (tid == 0){
        int nxt = CAND;
        for (int c = NC-1; c >= 0; --c){
            int f = firstc[c];
            if (f == 0x7FFFFFFF){ g_segstart[b*NC+c] = 0; g_segcnt[b*NC+c] = 0; }
            else { g_segstart[b*NC+c] = f; g_segcnt[b*NC+c] = nxt - f; nxt = f; }
        }
    }
}

// per (image,class) greedy NMS on offset boxes (offset rounding matches reference!)
__global__ __launch_bounds__(256) void k_nms(){
    const int blk = blockIdx.x, b = blk/NC, c = blk%NC;
    const int cnt = g_segcnt[b*NC + c];
    if (cnt == 0) return;
    const int start = g_segstart[b*NC + c];

    __shared__ float sx1[SHB], sy1[SHB], sx2[SHB], sy2[SHB];
    __shared__ unsigned char skeep[3008];
    __shared__ short srank[3008];
    const float off = (float)c * 2049.0f;
    const int tid = threadIdx.x;

    for (int m = tid; m < cnt; m += 256){
        int r = g_clsrank[b*CAND + start + m];
        srank[m] = (short)r;
        int pos = g_rank2pos[b*CAND + r];
        float x1 = __fadd_rn(g_boxv[(b*CAND+pos)*4+0], off);
        float y1 = __fadd_rn(g_boxv[(b*CAND+pos)*4+1], off);
        float x2 = __fadd_rn(g_boxv[(b*CAND+pos)*4+2], off);
        float y2 = __fadd_rn(g_boxv[(b*CAND+pos)*4+3], off);
        if (m < SHB){ sx1[m]=x1; sy1[m]=y1; sx2[m]=x2; sy2[m]=y2; }
        skeep[m] = 1;
    }
    __syncthreads();

    for (int i = 0; i < cnt; ++i){
        if (skeep[i]){
            float ix1, iy1, ix2, iy2;
            if (i < SHB){ ix1=sx1[i]; iy1=sy1[i]; ix2=sx2[i]; iy2=sy2[i]; }
            else {
                int pos = g_rank2pos[b*CAND + srank[i]];
                ix1 = __fadd_rn(g_boxv[(b*CAND+pos)*4+0], off);
                iy1 = __fadd_rn(g_boxv[(b*CAND+pos)*4+1], off);
                ix2 = __fadd_rn(g_boxv[(b*CAND+pos)*4+2], off);
                iy2 = __fadd_rn(g_boxv[(b*CAND+pos)*4+3], off);
            }
            float ia = __fmul_rn(__fsub_rn(ix2, ix1), __fsub_rn(iy2, iy1));
            for (int m = i + 1 + tid; m < cnt; m += 256){
                if (!skeep[m]) continue;
                float mx1, my1, mx2, my2;
                if (m < SHB){ mx1=sx1[m]; my1=sy1[m]; mx2=sx2[m]; my2=sy2[m]; }
                else {
                    int pos = g_rank2pos[b*CAND + srank[m]];
                    mx1 = __fadd_rn(g_boxv[(b*CAND+pos)*4+0], off);
                    my1 = __fadd_rn(g_boxv[(b*CAND+pos)*4+1], off);
                    mx2 = __fadd_rn(g_boxv[(b*CAND+pos)*4+2], off);
                    my2 = __fadd_rn(g_boxv[(b*CAND+pos)*4+3], off);
                }
                float xx1 = fmaxf(ix1, mx1), yy1 = fmaxf(iy1, my1);
                float xx2 = fminf(ix2, mx2), yy2 = fminf(iy2, my2);
                float w = fmaxf(__fsub_rn(xx2, xx1), 0.0f);
                float h = fmaxf(__fsub_rn(yy2, yy1), 0.0f);
                float inter = __fmul_rn(w, h);
                float ma  = __fmul_rn(__fsub_rn(mx2, mx1), __fsub_rn(my2, my1));
                float uni = __fsub_rn(__fadd_rn(ia, ma), inter);
                if (inter / uni > NMS_T) skeep[m] = 0;
            }
        }
        __syncthreads();
    }
    for (int m = tid; m < cnt; m += 256)
        g_keep[b*CAND + srank[m]] = skeep[m];
}

// per image: emit top-100 kept (sorted order), pad with non-kept (sorted order, score -1)
__global__ __launch_bounds__(1024) void k_final(float* __restrict__ out){
    const int b = blockIdx.x, tid = threadIdx.x;
    __shared__ int ps[1024];

    int flags[3]; int loc = 0;
    #pragma unroll
    for (int w = 0; w < 3; ++w){
        int r = tid*3 + w;
        int f = 0;
        if (r < CAND)
            f = (g_keep[b*CAND + r] && (g_ss[b*CAND + r] > 0.0f)) ? 1 : 0;
        flags[w] = f; loc += f;
    }
    ps[tid] = loc; __syncthreads();
    for (int o = 1; o < 1024; o <<= 1){
        int t = (tid >= o) ? ps[tid - o] : 0;
        __syncthreads();
        ps[tid] += t;
        __syncthreads();
    }
    const int excl  = ps[tid] - loc;
    const int total = ps[1023];

    int s = excl;
    #pragma unroll
    for (int w = 0; w < 3; ++w){
        int r = tid*3 + w;
        if (r < CAND && flags[w]){
            if (s < DETS){
                int pos = g_rank2pos[b*CAND + r];
                float* ob = out + ((size_t)b*DETS + s)*4;
                ob[0] = g_boxv[(b*CAND+pos)*4+0];
                ob[1] = g_boxv[(b*CAND+pos)*4+1];
                ob[2] = g_boxv[(b*CAND+pos)*4+2];
                ob[3] = g_boxv[(b*CAND+pos)*4+3];
                out[NB*DETS*4 + b*DETS + s]           = g_ss[b*CAND + r];
                out[NB*DETS*4 + NB*DETS + b*DETS + s] = (float)g_labelv[b*CAND+pos];
            }
            s++;
        }
    }
    const int base = (total < DETS) ? total : DETS;
    __syncthreads();

    // padding pass: non-kept in rank order
    loc = 0; int pflags[3];
    #pragma unroll
    for (int w = 0; w < 3; ++w){
        int r = tid*3 + w;
        int f = (r < CAND && !flags[w]) ? 1 : 0;
        pflags[w] = f; loc += f;
    }
    ps[tid] = loc; __syncthreads();
    for (int o = 1; o < 1024; o <<= 1){
        int t = (tid >= o) ? ps[tid - o] : 0;
        __syncthreads();
        ps[tid] += t;
        __syncthreads();
    }
    int pexcl = ps[tid] - loc;
    s = base + pexcl;
    #pragma unroll
    for (int w = 0; w < 3; ++w){
        int r = tid*3 + w;
        if (r < CAND && pflags[w]){
            if (s < DETS){
                int pos = g_rank2pos[b*CAND + r];
                float* ob = out + ((size_t)b*DETS + s)*4;
                ob[0] = g_boxv[(b*CAND+pos)*4+0];
                ob[1] = g_boxv[(b*CAND+pos)*4+1];
                ob[2] = g_boxv[(b*CAND+pos)*4+2];
                ob[3] = g_boxv[(b*CAND+pos)*4+3];
                out[NB*DETS*4 + b*DETS + s]           = -1.0f;
                out[NB*DETS*4 + NB*DETS + b*DETS + s] = (float)g_labelv[b*CAND+pos];
            }
            s++;
        }
    }
}

// ---------------- host ----------------
extern "C" void kernel_launch(void* const* d_in, const int* in_sizes, int n_in,
                              void* d_out, int out_size){
    const float *cls[3], *reg[3], *ctr[3], *anc[3];
    if (n_in >= 12 && in_sizes[0] == 2621440 && in_sizes[1] == 131072){
        // interleaved: cls0,reg0,ctr0,anc0, cls1,...  (setup_inputs dict order)
        for (int l = 0; l < 3; ++l){
            cls[l] = (const float*)d_in[4*l + 0];
            reg[l] = (const float*)d_in[4*l + 1];
            ctr[l] = (const float*)d_in[4*l + 2];
            anc[l] = (const float*)d_in[4*l + 3];
        }
    } else if (n_in >= 12 && in_sizes[0] == 16384){
        // alphabetical: anc0..2, cls0..2, ctr0..2, reg0..2
        for (int l = 0; l < 3; ++l){
            anc[l] = (const float*)d_in[0 + l];
            cls[l] = (const float*)d_in[3 + l];
            ctr[l] = (const float*)d_in[6 + l];
            reg[l] = (const float*)d_in[9 + l];
        }
    } else {
        // grouped (reference signature order): cls0..2, reg0..2, ctr0..2, anc0..2
        for (int l = 0; l < 3; ++l){
            cls[l] = (const float*)d_in[0 + l];
            reg[l] = (const float*)d_in[3 + l];
            ctr[l] = (const float*)d_in[6 + l];
            anc[l] = (const float*)d_in[9 + l];
        }
    }

    dim3 g1((TOT + 255)/256, NB);
    k_init<<<24, 256>>>();
    k_scores<<<g1, 256>>>(cls[0], cls[1], cls[2], ctr[0], ctr[1], ctr[2]);
    k_pivot<<<1, 32>>>(24);
    k_hist<<<g1, 256>>>(16);  k_pivot<<<1, 32>>>(16);
    k_hist<<<g1, 256>>>(8);   k_pivot<<<1, 32>>>(8);
    k_hist<<<g1, 256>>>(0);   k_pivot<<<1, 32>>>(0);
    k_collect<<<g1, 256>>>();
    k_sortlevel<<<NPAIR, 1024>>>(reg[0], reg[1], reg[2], anc[0], anc[1], anc[2]);
    k_sortimage<<<NB, 1024>>>();
    k_nms<<<NB*NC, 256>>>();
    k_final<<<NB, 1024>>>((float*)d_out);
}

// round 3
// speedup vs baseline: 1.7177x; 1.7177x over previous
#include <cuda_runtime.h>
#include <stdint.h>

// ---------------- problem constants ----------------
#define NC    80
#define A0    4096
#define A1    1024
#define A2    256
#define N0    (A0*NC)          // 327680
#define N1    (A1*NC)          // 81920
#define N2    (A2*NC)          // 20480
#define TOT   (N0+N1+N2)       // 430080 per image
#define OFF1  N0
#define OFF2  (N0+N1)
#define NB    8
#define TOPK  1000
#define NLVL  3
#define NPAIR (NB*NLVL)        // 24
#define CAND  3000
#define DETS  100
#define IMGSZ 2048.0f
#define NMS_T 0.6f
#define CAP   4096
#define SHB   2048
#define BINS  16512            // key16 range: ~f2k(w>=1) >> 16 in [127, 16511]

// ---------------- scratch (device globals; no allocations) ----------------
__device__ uint32_t g_hist16[NPAIR*BINS];                 // ~1.6 MB
__device__ __align__(16) unsigned short g_keys16[NB*TOT]; // ~6.9 MB
__device__ float    g_score[NB*CAND];
__device__ int      g_labelv[NB*CAND];
__device__ float    g_boxv[NB*CAND*4];
__device__ int      g_rank2pos[NB*CAND];
__device__ float    g_ss[NB*CAND];
__device__ int      g_lab_ranked[NB*CAND];
__device__ unsigned char g_keep[NB*CAND];

// ---------------- helpers ----------------
__device__ __forceinline__ uint32_t f2k(float f){
    uint32_t u = __float_as_uint(f);
    return (u & 0x80000000u) ? ~u : (u | 0x80000000u);
}
__device__ __forceinline__ float k2f(uint32_t k){
    uint32_t u = (k & 0x80000000u) ? (k ^ 0x80000000u) : ~k;
    return __uint_as_float(u);
}
// exact path: XLA logistic(x) == 0.5 + 0.5*tanh(0.5*x)
__device__ __forceinline__ float sigm(float x){
    return 0.5f*tanhf(0.5f*x) + 0.5f;
}

// generic bitonic sort (ascending) of n (2048 or 4096) u64s, blockDim = 1024
__device__ __forceinline__ void bitonicN(unsigned long long* s, int n){
    const int tid = threadIdx.x;
    const int per = n >> 10;
    for (int k = 2; k <= n; k <<= 1){
        for (int j = k >> 1; j > 0; j >>= 1){
            __syncthreads();
            for (int w = 0; w < per; ++w){
                int i   = tid + (w << 10);
                int ixj = i ^ j;
                if (ixj > i){
                    unsigned long long a = s[i], bb = s[ixj];
                    bool up = ((i & k) == 0);
                    if ((a > bb) == up){ s[i] = bb; s[ixj] = a; }
                }
            }
        }
    }
    __syncthreads();
}

// ---------------- kernels ----------------
__global__ void k_init(){
    int t = blockIdx.x*blockDim.x + threadIdx.x;
    if (t < NPAIR*BINS) g_hist16[t] = 0;
}

// one fused pass: surrogate keys (16-bit) + fine histogram
// surrogate: w = (1+e^-c)(1+e^-t); score order == descending w (monotone)
__global__ __launch_bounds__(256) void k_scores(
    const float* __restrict__ cls0, const float* __restrict__ cls1, const float* __restrict__ cls2,
    const float* __restrict__ ctr0, const float* __restrict__ ctr1, const float* __restrict__ ctr2)
{
    const int b = blockIdx.y;
    const int base = blockIdx.x*2048 + threadIdx.x*8;   // blocks never straddle levels; 8-runs never straddle anchors
    int l, j0, A; const float* cls; const float* ctr;
    if (base < OFF1){ l = 0; j0 = base;        cls = cls0; ctr = ctr0; A = A0; }
    else if (base < OFF2){ l = 1; j0 = base - OFF1; cls = cls1; ctr = ctr1; A = A1; }
    else { l = 2; j0 = base - OFF2; cls = cls2; ctr = ctr2; A = A2; }
    const int pair = b*NLVL + l;

    float tv = __ldg(ctr + (size_t)b*A + j0/NC);
    float et = __expf(-tv);
    float vt = et + 1.0f;

    const float4* cp = (const float4*)(cls + (size_t)b*A*NC + j0);
    float4 ca = cp[0], cb = cp[1];
    float cv[8] = {ca.x, ca.y, ca.z, ca.w, cb.x, cb.y, cb.z, cb.w};

    uint32_t* hrow = g_hist16 + (size_t)pair*BINS;
    uint32_t ks[8];
    #pragma unroll
    for (int e = 0; e < 8; ++e){
        float ec = __expf(-cv[e]);
        float w  = fmaf(ec, vt, vt);                    // (1+ec)*vt
        uint32_t kp  = (~__float_as_uint(w)) & 0x7FFFFFFFu;  // = ~f2k(w), w>0
        uint32_t k16 = kp >> 16;
        ks[e] = k16;
        atomicAdd(hrow + k16, 1u);
    }
    uint4 pk;
    pk.x = ks[0] | (ks[1] << 16);
    pk.y = ks[2] | (ks[3] << 16);
    pk.z = ks[4] | (ks[5] << 16);
    pk.w = ks[6] | (ks[7] << 16);
    *(uint4*)(g_keys16 + (size_t)b*TOT + base) = pk;
}

// per (image,level): pivot scan + collect + exact rescore + sort + decode top-1000
__global__ __launch_bounds__(1024) void k_sortlevel(
    const float* __restrict__ cls0, const float* __restrict__ cls1, const float* __restrict__ cls2,
    const float* __restrict__ ctr0, const float* __restrict__ ctr1, const float* __restrict__ ctr2,
    const float* __restrict__ reg0, const float* __restrict__ reg1, const float* __restrict__ reg2,
    const float* __restrict__ anc0, const float* __restrict__ anc1, const float* __restrict__ anc2)
{
    __shared__ unsigned long long s64[CAP];   // 32 KB
    __shared__ uint32_t ssum[1024];
    __shared__ int sP, sCum, sThresh, sCnt;

    const int p = blockIdx.x, b = p/NLVL, l = p%NLVL;
    const int tid = threadIdx.x;
    int A, offl; const float *cls, *ctr, *reg, *anc;
    if (l == 0){ A=A0; offl=0;    cls=cls0; ctr=ctr0; reg=reg0; anc=anc0; }
    else if (l == 1){ A=A1; offl=OFF1; cls=cls1; ctr=ctr1; reg=reg1; anc=anc1; }
    else { A=A2; offl=OFF2; cls=cls2; ctr=ctr2; reg=reg2; anc=anc2; }
    const uint32_t* h = g_hist16 + (size_t)p*BINS;

    // ---- phase A: pivot bin (highest bin T with cum(bins>=T) >= TOPK), extend 1 bin if safe
    int lo = tid*17; if (lo > BINS) lo = BINS;
    int hi = lo + 17; if (hi > BINS) hi = BINS;
    uint32_t own = 0;
    for (int i = lo; i < hi; ++i) own += h[i];
    ssum[tid] = own; __syncthreads();
    for (int off = 1; off < 1024; off <<= 1){
        uint32_t v = (tid + off < 1024) ? ssum[tid + off] : 0;
        __syncthreads(); ssum[tid] += v; __syncthreads();
    }
    uint32_t cumAbove = (tid < 1023) ? ssum[tid + 1] : 0;
    if (tid == 0) sCnt = 0;
    if (cumAbove < TOPK && cumAbove + own >= TOPK){
        uint32_t run = cumAbove; int P = lo;
        for (int i = hi - 1; i >= lo; --i){ run += h[i]; if (run >= TOPK){ P = i; break; } }
        sP = P; sCum = (int)run;
    }
    __syncthreads();
    if (tid == 0){
        int P = sP, ext = P;
        if (P > 0 && sCum + (int)h[P-1] <= CAP) ext = P - 1;
        sThresh = ext;
    }
    __syncthreads();
    const uint32_t thr = (uint32_t)sThresh;

    // ---- phase B: collect candidate indices (order arbitrary; fixed by sort)
    const uint4* kp = (const uint4*)(g_keys16 + (size_t)b*TOT + offl);
    const int num8 = (A*NC)/8;
    for (int v = tid; v < num8; v += 1024){
        uint4 q = kp[v];
        uint32_t wv[4] = {q.x, q.y, q.z, q.w};
        #pragma unroll
        for (int u = 0; u < 4; ++u){
            uint32_t l16 = wv[u] & 0xFFFFu, h16 = wv[u] >> 16;
            if (l16 >= thr){ int pos = atomicAdd(&sCnt, 1); if (pos < CAP) s64[pos] = (unsigned long long)(v*8 + u*2); }
            if (h16 >= thr){ int pos = atomicAdd(&sCnt, 1); if (pos < CAP) s64[pos] = (unsigned long long)(v*8 + u*2 + 1); }
        }
    }
    __syncthreads();
    int cnt = sCnt; if (cnt > CAP) cnt = CAP;
    const int SORTN = (cnt <= 2048) ? 2048 : 4096;

    // ---- phase C: exact XLA-matching scores for candidates; build (~key, idx) composites
    for (int i = tid; i < SORTN; i += 1024){
        unsigned long long comp = 0xFFFFFFFFFFFFFFFFULL;
        if (i < cnt){
            int j = (int)(uint32_t)s64[i];
            float c  = cls[(size_t)b*A*NC + j];
            float tt = ctr[(size_t)b*A + j/NC];
            float sa = sigm(c);
            float st = sigm(tt);
            float sc = sqrtf(__fmul_rn(sa, st));
            uint32_t key = (sc > 0.2f) ? f2k(sc) : 0x407FFFFFu;   // f2k(-1.0f)
            comp = ((unsigned long long)(~key) << 32) | (uint32_t)j;
        }
        s64[i] = comp;
    }
    bitonicN(s64, SORTN);

    // ---- phase E: emit sorted top-1000 + decode boxes
    if (tid < TOPK){
        unsigned long long cc = s64[tid];
        uint32_t key = ~(uint32_t)(cc >> 32);
        uint32_t idx = (uint32_t)cc;
        float sc = k2f(key);
        int aidx = (int)(idx / NC);
        int lab  = (int)(idx % NC);

        const int pos = b*CAND + l*TOPK + tid;
        g_score[pos]  = sc;
        g_labelv[pos] = lab;

        const float* a = anc + (size_t)aidx*4;
        const float* r = reg + ((size_t)b*A + aidx)*4;
        float a0 = a[0], a1 = a[1], a2 = a[2], a3 = a[3];
        float cx = __fmul_rn(0.5f, __fadd_rn(a0, a2));
        float cy = __fmul_rn(0.5f, __fadd_rn(a1, a3));
        float w  = __fsub_rn(a2, a0);
        float hh = __fsub_rn(a3, a1);
        float x1 = __fsub_rn(cx, __fmul_rn(r[0], w));
        float y1 = __fsub_rn(cy, __fmul_rn(r[1], hh));
        float x2 = __fadd_rn(cx, __fmul_rn(r[2], w));
        float y2 = __fadd_rn(cy, __fmul_rn(r[3], hh));
        x1 = fminf(fmaxf(x1, 0.0f), IMGSZ);
        y1 = fminf(fmaxf(y1, 0.0f), IMGSZ);
        x2 = fminf(fmaxf(x2, 0.0f), IMGSZ);
        y2 = fminf(fmaxf(y2, 0.0f), IMGSZ);
        g_boxv[pos*4+0] = x1; g_boxv[pos*4+1] = y1;
        g_boxv[pos*4+2] = x2; g_boxv[pos*4+3] = y2;
    }
}

// per image: 3-way merge of the 3 sorted level lists (exact top_k tie rules)
__global__ __launch_bounds__(1024) void k_merge(){
    __shared__ float sc[CAND];
    const int b = blockIdx.x, tid = threadIdx.x;
    for (int t = tid; t < CAND; t += 1024) sc[t] = g_score[b*CAND + t];
    __syncthreads();
    for (int t = tid; t < CAND; t += 1024){
        int l = t / TOPK, i = t % TOPK;
        float x = sc[t];
        int rank = i;
        #pragma unroll
        for (int l2 = 0; l2 < NLVL; ++l2){
            if (l2 == l) continue;
            const float* arr = sc + l2*TOPK;
            int lo = 0, hi = TOPK;
            if (l2 < l){      // elements >= x precede (earlier global idx wins ties)
                while (lo < hi){ int m = (lo + hi) >> 1; if (arr[m] >= x) lo = m + 1; else hi = m; }
            } else {          // only elements > x precede
                while (lo < hi){ int m = (lo + hi) >> 1; if (arr[m] >  x) lo = m + 1; else hi = m; }
            }
            rank += lo;
        }
        g_rank2pos[b*CAND + rank]   = t;
        g_ss[b*CAND + rank]         = x;
        g_lab_ranked[b*CAND + rank] = g_labelv[b*CAND + t];
    }
}

// per (image,class): build class list (warp ballot, rank-ordered) + greedy NMS
__global__ __launch_bounds__(256) void k_nms(){
    const int blk = blockIdx.x, b = blk/NC, c = blk%NC;
    __shared__ short slist[3008];
    __shared__ int scount;
    __shared__ float sx1[SHB], sy1[SHB], sx2[SHB], sy2[SHB];
    __shared__ unsigned char skeep[3008];
    const int tid = threadIdx.x, lane = tid & 31;

    if (tid < 32){
        int basec = 0;
        for (int r0 = 0; r0 < CAND; r0 += 32){
            int r = r0 + lane;
            int lab = (r < CAND) ? g_lab_ranked[b*CAND + r] : -1;
            bool m = (lab == c);
            unsigned bal = __ballot_sync(0xFFFFFFFFu, m);
            if (m) slist[basec + __popc(bal & ((1u << lane) - 1u))] = (short)r;
            basec += __popc(bal);
        }
        if (lane == 0) scount = basec;
    }
    __syncthreads();
    const int cnt = scount;
    if (cnt == 0) return;

    const float off = (float)c * 2049.0f;
    for (int m = tid; m < cnt; m += 256){
        int r = slist[m];
        int pos = g_rank2pos[b*CAND + r];
        float x1 = __fadd_rn(g_boxv[(b*CAND+pos)*4+0], off);
        float y1 = __fadd_rn(g_boxv[(b*CAND+pos)*4+1], off);
        float x2 = __fadd_rn(g_boxv[(b*CAND+pos)*4+2], off);
        float y2 = __fadd_rn(g_boxv[(b*CAND+pos)*4+3], off);
        if (m < SHB){ sx1[m]=x1; sy1[m]=y1; sx2[m]=x2; sy2[m]=y2; }
        skeep[m] = 1;
    }
    __syncthreads();

    for (int i = 0; i < cnt; ++i){
        if (skeep[i]){
            float ix1, iy1, ix2, iy2;
            if (i < SHB){ ix1=sx1[i]; iy1=sy1[i]; ix2=sx2[i]; iy2=sy2[i]; }
            else {
                int pos = g_rank2pos[b*CAND + slist[i]];
                ix1 = __fadd_rn(g_boxv[(b*CAND+pos)*4+0], off);
                iy1 = __fadd_rn(g_boxv[(b*CAND+pos)*4+1], off);
                ix2 = __fadd_rn(g_boxv[(b*CAND+pos)*4+2], off);
                iy2 = __fadd_rn(g_boxv[(b*CAND+pos)*4+3], off);
            }
            float ia = __fmul_rn(__fsub_rn(ix2, ix1), __fsub_rn(iy2, iy1));
            for (int m = i + 1 + tid; m < cnt; m += 256){
                if (!skeep[m]) continue;
                float mx1, my1, mx2, my2;
                if (m < SHB){ mx1=sx1[m]; my1=sy1[m]; mx2=sx2[m]; my2=sy2[m]; }
                else {
                    int pos = g_rank2pos[b*CAND + slist[m]];
                    mx1 = __fadd_rn(g_boxv[(b*CAND+pos)*4+0], off);
                    my1 = __fadd_rn(g_boxv[(b*CAND+pos)*4+1], off);
                    mx2 = __fadd_rn(g_boxv[(b*CAND+pos)*4+2], off);
                    my2 = __fadd_rn(g_boxv[(b*CAND+pos)*4+3], off);
                }
                float xx1 = fmaxf(ix1, mx1), yy1 = fmaxf(iy1, my1);
                float xx2 = fminf(ix2, mx2), yy2 = fminf(iy2, my2);
                float w = fmaxf(__fsub_rn(xx2, xx1), 0.0f);
                float hh = fmaxf(__fsub_rn(yy2, yy1), 0.0f);
                float inter = __fmul_rn(w, hh);
                float ma  = __fmul_rn(__fsub_rn(mx2, mx1), __fsub_rn(my2, my1));
                float uni = __fsub_rn(__fadd_rn(ia, ma), inter);
                if (inter / uni > NMS_T) skeep[m] = 0;
            }
        }
        __syncthreads();
    }
    for (int m = tid; m < cnt; m += 256)
        g_keep[b*CAND + slist[m]] = skeep[m];
}

// per image: emit top-100 kept (rank order), pad with non-kept (rank order, score -1)
__global__ __launch_bounds__(1024) void k_final(float* __restrict__ out){
    const int b = blockIdx.x, tid = threadIdx.x;
    __shared__ int ps[1024];

    int flags[3]; int loc = 0;
    #pragma unroll
    for (int w = 0; w < 3; ++w){
        int r = tid*3 + w;
        int f = 0;
        if (r < CAND)
            f = (g_keep[b*CAND + r] && (g_ss[b*CAND + r] > 0.0f)) ? 1 : 0;
        flags[w] = f; loc += f;
    }
    ps[tid] = loc; __syncthreads();
    for (int o = 1; o < 1024; o <<= 1){
        int t = (tid >= o) ? ps[tid - o] : 0;
        __syncthreads();
        ps[tid] += t;
        __syncthreads();
    }
    const int excl  = ps[tid] - loc;
    const int total = ps[1023];

    int s = excl;
    #pragma unroll
    for (int w = 0; w < 3; ++w){
        int r = tid*3 + w;
        if (r < CAND && flags[w]){
            if (s < DETS){
                int pos = g_rank2pos[b*CAND + r];
                float* ob = out + ((size_t)b*DETS + s)*4;
                ob[0] = g_boxv[(b*CAND+pos)*4+0];
                ob[1] = g_boxv[(b*CAND+pos)*4+1];
                ob[2] = g_boxv[(b*CAND+pos)*4+2];
                ob[3] = g_boxv[(b*CAND+pos)*4+3];
                out[NB*DETS*4 + b*DETS + s]           = g_ss[b*CAND + r];
                out[NB*DETS*4 + NB*DETS + b*DETS + s] = (float)g_labelv[b*CAND+pos];
            }
            s++;
        }
    }
    const int base = (total < DETS) ? total : DETS;
    __syncthreads();

    loc = 0; int pflags[3];
    #pragma unroll
    for (int w = 0; w < 3; ++w){
        int r = tid*3 + w;
        int f = (r < CAND && !flags[w]) ? 1 : 0;
        pflags[w] = f; loc += f;
    }
    ps[tid] = loc; __syncthreads();
    for (int o = 1; o < 1024; o <<= 1){
        int t = (tid >= o) ? ps[tid - o] : 0;
        __syncthreads();
        ps[tid] += t;
        __syncthreads();
    }
    int pexcl = ps[tid] - loc;
    s = base + pexcl;
    #pragma unroll
    for (int w = 0; w < 3; ++w){
        int r = tid*3 + w;
        if (r < CAND && pflags[w]){
            if (s < DETS){
                int pos = g_rank2pos[b*CAND + r];
                float* ob = out + ((size_t)b*DETS + s)*4;
                ob[0] = g_boxv[(b*CAND+pos)*4+0];
                ob[1] = g_boxv[(b*CAND+pos)*4+1];
                ob[2] = g_boxv[(b*CAND+pos)*4+2];
                ob[3] = g_boxv[(b*CAND+pos)*4+3];
                out[NB*DETS*4 + b*DETS + s]           = -1.0f;
                out[NB*DETS*4 + NB*DETS + b*DETS + s] = (float)g_labelv[b*CAND+pos];
            }
            s++;
        }
    }
}

// ---------------- host ----------------
extern "C" void kernel_launch(void* const* d_in, const int* in_sizes, int n_in,
                              void* d_out, int out_size){
    const float *cls[3], *reg[3], *ctr[3], *anc[3];
    if (n_in >= 12 && in_sizes[0] == 2621440 && in_sizes[1] == 131072){
        for (int l = 0; l < 3; ++l){
            cls[l] = (const float*)d_in[4*l + 0];
            reg[l] = (const float*)d_in[4*l + 1];
            ctr[l] = (const float*)d_in[4*l + 2];
            anc[l] = (const float*)d_in[4*l + 3];
        }
    } else if (n_in >= 12 && in_sizes[0] == 16384){
        for (int l = 0; l < 3; ++l){
            anc[l] = (const float*)d_in[0 + l];
            cls[l] = (const float*)d_in[3 + l];
            ctr[l] = (const float*)d_in[6 + l];
            reg[l] = (const float*)d_in[9 + l];
        }
    } else {
        for (int l = 0; l < 3; ++l){
            cls[l] = (const float*)d_in[0 + l];
            reg[l] = (const float*)d_in[3 + l];
            ctr[l] = (const float*)d_in[6 + l];
            anc[l] = (const float*)d_in[9 + l];
        }
    }

    k_init<<<(NPAIR*BINS + 1023)/1024, 1024>>>();
    k_scores<<<dim3(TOT/2048, NB), 256>>>(cls[0], cls[1], cls[2], ctr[0], ctr[1], ctr[2]);
    k_sortlevel<<<NPAIR, 1024>>>(cls[0], cls[1], cls[2], ctr[0], ctr[1], ctr[2],
                                 reg[0], reg[1], reg[2], anc[0], anc[1], anc[2]);
    k_merge<<<NB, 1024>>>();
    k_nms<<<NB*NC, 256>>>();
    k_final<<<NB, 1024>>>((float*)d_out);
}

// round 4
// speedup vs baseline: 3.4562x; 2.0121x over previous
#include <cuda_runtime.h>
#include <stdint.h>

// ---------------- problem constants ----------------
#define NC    80
#define A0    4096
#define A1    1024
#define A2    256
#define N0    (A0*NC)          // 327680
#define N1    (A1*NC)          // 81920
#define N2    (A2*NC)          // 20480
#define TOT   (N0+N1+N2)       // 430080 per image
#define OFF1  N0
#define OFF2  (N0+N1)
#define NB    8
#define TOPK  1000
#define NLVL  3
#define NPAIR (NB*NLVL)        // 24
#define CAND  3000
#define DETS  100
#define IMGSZ 2048.0f
#define NMS_T 0.6f
#define CAP   4096
#define SHB   2048
#define BINS  16512            // key16 range: ~f2k(w>=1) >> 16 in [127, 16511]

// dynamic smem for k_sortlevel: union of hist (BINS u32) and sort buffer (CAP u64)
#define DYNBYTES ((BINS*4 > CAP*8) ? BINS*4 : CAP*8)

// ---------------- scratch (device globals; no allocations) ----------------
__device__ __align__(16) unsigned short g_keys16[NB*TOT]; // ~6.9 MB
__device__ float    g_score[NB*CAND];
__device__ int      g_labelv[NB*CAND];
__device__ float    g_boxv[NB*CAND*4];
__device__ int      g_rank2pos[NB*CAND];
__device__ float    g_ss[NB*CAND];
__device__ int      g_lab_ranked[NB*CAND];
__device__ unsigned char g_keep[NB*CAND];

// ---------------- helpers ----------------
__device__ __forceinline__ uint32_t f2k(float f){
    uint32_t u = __float_as_uint(f);
    return (u & 0x80000000u) ? ~u : (u | 0x80000000u);
}
__device__ __forceinline__ float k2f(uint32_t k){
    uint32_t u = (k & 0x80000000u) ? (k ^ 0x80000000u) : ~k;
    return __uint_as_float(u);
}
// exact path: XLA logistic(x) == 0.5 + 0.5*tanh(0.5*x)
__device__ __forceinline__ float sigm(float x){
    return 0.5f*tanhf(0.5f*x) + 0.5f;
}

// bitonic sort (ascending) of n (2048 or 4096) u64s, blockDim = 1024
__device__ __forceinline__ void bitonicN(unsigned long long* s, int n){
    const int tid = threadIdx.x;
    const int per = n >> 10;
    for (int k = 2; k <= n; k <<= 1){
        for (int j = k >> 1; j > 0; j >>= 1){
            __syncthreads();
            for (int w = 0; w < per; ++w){
                int i   = tid + (w << 10);
                int ixj = i ^ j;
                if (ixj > i){
                    unsigned long long a = s[i], bb = s[ixj];
                    bool up = ((i & k) == 0);
                    if ((a > bb) == up){ s[i] = bb; s[ixj] = a; }
                }
            }
        }
    }
    __syncthreads();
}

// ---------------- kernels ----------------
// pure streaming pass: surrogate 16-bit keys, NO atomics
// surrogate: w = (1+e^-c)(1+e^-t); score order == descending w (monotone)
__global__ __launch_bounds__(256) void k_scores(
    const float* __restrict__ cls0, const float* __restrict__ cls1, const float* __restrict__ cls2,
    const float* __restrict__ ctr0, const float* __restrict__ ctr1, const float* __restrict__ ctr2)
{
    const int b = blockIdx.y;
    const int base = blockIdx.x*2048 + threadIdx.x*8;   // blocks never straddle levels; 8-runs never straddle anchors
    int j0, A; const float* cls; const float* ctr;
    if (base < OFF1){ j0 = base;        cls = cls0; ctr = ctr0; A = A0; }
    else if (base < OFF2){ j0 = base - OFF1; cls = cls1; ctr = ctr1; A = A1; }
    else { j0 = base - OFF2; cls = cls2; ctr = ctr2; A = A2; }

    float tv = __ldg(ctr + (size_t)b*A + j0/NC);
    float et = __expf(-tv);
    float vt = et + 1.0f;

    const float4* cp = (const float4*)(cls + (size_t)b*A*NC + j0);
    float4 ca = cp[0], cb = cp[1];
    float cv[8] = {ca.x, ca.y, ca.z, ca.w, cb.x, cb.y, cb.z, cb.w};

    uint32_t ks[8];
    #pragma unroll
    for (int e = 0; e < 8; ++e){
        float ec = __expf(-cv[e]);
        float w  = fmaf(ec, vt, vt);                        // (1+ec)*vt
        ks[e] = ((~__float_as_uint(w)) & 0x7FFFFFFFu) >> 16; // = ~f2k(w)>>16, w>0
    }
    uint4 pk;
    pk.x = ks[0] | (ks[1] << 16);
    pk.y = ks[2] | (ks[3] << 16);
    pk.z = ks[4] | (ks[5] << 16);
    pk.w = ks[6] | (ks[7] << 16);
    *(uint4*)(g_keys16 + (size_t)b*TOT + base) = pk;
}

// per (image,level): shared hist + pivot + collect + exact rescore + sort + decode top-1000
__global__ __launch_bounds__(1024) void k_sortlevel(
    const float* __restrict__ cls0, const float* __restrict__ cls1, const float* __restrict__ cls2,
    const float* __restrict__ ctr0, const float* __restrict__ ctr1, const float* __restrict__ ctr2,
    const float* __restrict__ reg0, const float* __restrict__ reg1, const float* __restrict__ reg2,
    const float* __restrict__ anc0, const float* __restrict__ anc1, const float* __restrict__ anc2)
{
    extern __shared__ unsigned char dynsmem[];
    uint32_t*           hist = (uint32_t*)dynsmem;           // phase A (BINS u32)
    unsigned long long* s64  = (unsigned long long*)dynsmem; // phase B+ (CAP u64), aliases hist
    __shared__ uint32_t ssum[1024];
    __shared__ int sP, sCum, sThresh, sCnt;

    const int p = blockIdx.x, b = p/NLVL, l = p%NLVL;
    const int tid = threadIdx.x;
    int A, offl; const float *cls, *ctr, *reg, *anc;
    if (l == 0){ A=A0; offl=0;    cls=cls0; ctr=ctr0; reg=reg0; anc=anc0; }
    else if (l == 1){ A=A1; offl=OFF1; cls=cls1; ctr=ctr1; reg=reg1; anc=anc1; }
    else { A=A2; offl=OFF2; cls=cls2; ctr=ctr2; reg=reg2; anc=anc2; }

    // ---- phase H: build local histogram from this pair's key slice (L2-resident)
    for (int t = tid; t < BINS; t += 1024) hist[t] = 0;
    __syncthreads();
    const uint4* kp = (const uint4*)(g_keys16 + (size_t)b*TOT + offl);
    const int num8 = (A*NC)/8;
    for (int v = tid; v < num8; v += 1024){
        uint4 q = kp[v];
        uint32_t wv[4] = {q.x, q.y, q.z, q.w};
        #pragma unroll
        for (int u = 0; u < 4; ++u){
            atomicAdd(hist + (wv[u] & 0xFFFFu), 1u);
            atomicAdd(hist + (wv[u] >> 16),     1u);
        }
    }
    __syncthreads();

    // ---- phase A: pivot bin (highest T with cum(bins>=T) >= TOPK), extend 1 bin if safe
    int lo = tid*17; if (lo > BINS) lo = BINS;
    int hi = lo + 17; if (hi > BINS) hi = BINS;
    uint32_t own = 0;
    for (int i = lo; i < hi; ++i) own += hist[i];
    ssum[tid] = own; __syncthreads();
    for (int off = 1; off < 1024; off <<= 1){
        uint32_t v = (tid + off < 1024) ? ssum[tid + off] : 0;
        __syncthreads(); ssum[tid] += v; __syncthreads();
    }
    uint32_t cumAbove = (tid < 1023) ? ssum[tid + 1] : 0;
    if (tid == 0) sCnt = 0;
    if (cumAbove < TOPK && cumAbove + own >= TOPK){
        uint32_t run = cumAbove; int P = lo;
        for (int i = hi - 1; i >= lo; --i){ run += hist[i]; if (run >= TOPK){ P = i; break; } }
        sP = P; sCum = (int)run;
    }
    __syncthreads();
    if (tid == 0){
        int P = sP, ext = P;
        if (P > 0 && sCum + (int)hist[P-1] <= CAP) ext = P - 1;
        sThresh = ext;
    }
    __syncthreads();
    const uint32_t thr = (uint32_t)sThresh;
    __syncthreads();   // all hist reads done before s64 overwrites it

    // ---- phase B: collect candidate indices (order arbitrary; fixed by sort)
    for (int v = tid; v < num8; v += 1024){
        uint4 q = kp[v];
        uint32_t wv[4] = {q.x, q.y, q.z, q.w};
        #pragma unroll
        for (int u = 0; u < 4; ++u){
            uint32_t l16 = wv[u] & 0xFFFFu, h16 = wv[u] >> 16;
            if (l16 >= thr){ int pos = atomicAdd(&sCnt, 1); if (pos < CAP) s64[pos] = (unsigned long long)(v*8 + u*2); }
            if (h16 >= thr){ int pos = atomicAdd(&sCnt, 1); if (pos < CAP) s64[pos] = (unsigned long long)(v*8 + u*2 + 1); }
        }
    }
    __syncthreads();
    int cnt = sCnt; if (cnt > CAP) cnt = CAP;
    const int SORTN = (cnt <= 2048) ? 2048 : 4096;

    // ---- phase C: exact XLA-matching scores; build (~key, idx) composites
    for (int i = tid; i < SORTN; i += 1024){
        unsigned long long comp = 0xFFFFFFFFFFFFFFFFULL;
        if (i < cnt){
            int j = (int)(uint32_t)s64[i];
            float c  = cls[(size_t)b*A*NC + j];
            float tt = ctr[(size_t)b*A + j/NC];
            float sa = sigm(c);
            float st = sigm(tt);
            float sc = sqrtf(__fmul_rn(sa, st));
            uint32_t key = (sc > 0.2f) ? f2k(sc) : 0x407FFFFFu;   // f2k(-1.0f)
            comp = ((unsigned long long)(~key) << 32) | (uint32_t)j;
        }
        s64[i] = comp;
    }
    bitonicN(s64, SORTN);

    // ---- phase E: emit sorted top-1000 + decode boxes
    if (tid < TOPK){
        unsigned long long cc = s64[tid];
        uint32_t key = ~(uint32_t)(cc >> 32);
        uint32_t idx = (uint32_t)cc;
        float sc = k2f(key);
        int aidx = (int)(idx / NC);
        int lab  = (int)(idx % NC);

        const int pos = b*CAND + l*TOPK + tid;
        g_score[pos]  = sc;
        g_labelv[pos] = lab;

        const float* a = anc + (size_t)aidx*4;
        const float* r = reg + ((size_t)b*A + aidx)*4;
        float a0 = a[0], a1 = a[1], a2 = a[2], a3 = a[3];
        float cx = __fmul_rn(0.5f, __fadd_rn(a0, a2));
        float cy = __fmul_rn(0.5f, __fadd_rn(a1, a3));
        float w  = __fsub_rn(a2, a0);
        float hh = __fsub_rn(a3, a1);
        float x1 = __fsub_rn(cx, __fmul_rn(r[0], w));
        float y1 = __fsub_rn(cy, __fmul_rn(r[1], hh));
        float x2 = __fadd_rn(cx, __fmul_rn(r[2], w));
        float y2 = __fadd_rn(cy, __fmul_rn(r[3], hh));
        x1 = fminf(fmaxf(x1, 0.0f), IMGSZ);
        y1 = fminf(fmaxf(y1, 0.0f), IMGSZ);
        x2 = fminf(fmaxf(x2, 0.0f), IMGSZ);
        y2 = fminf(fmaxf(y2, 0.0f), IMGSZ);
        g_boxv[pos*4+0] = x1; g_boxv[pos*4+1] = y1;
        g_boxv[pos*4+2] = x2; g_boxv[pos*4+3] = y2;
    }
}

// per (image,level): rank this level's 1000 against the other two (exact top_k ties)
__global__ __launch_bounds__(1024) void k_merge(){
    __shared__ float sc[CAND];
    const int p = blockIdx.x, b = p/NLVL, l = p%NLVL;
    const int tid = threadIdx.x;
    for (int t = tid; t < CAND; t += 1024) sc[t] = g_score[b*CAND + t];
    __syncthreads();
    if (tid < TOPK){
        const int t = l*TOPK + tid;
        float x = sc[t];
        int rank = tid;
        #pragma unroll
        for (int l2 = 0; l2 < NLVL; ++l2){
            if (l2 == l) continue;
            const float* arr = sc + l2*TOPK;
            int lo = 0, hi = TOPK;
            if (l2 < l){      // elements >= x precede (earlier global idx wins ties)
                while (lo < hi){ int m = (lo + hi) >> 1; if (arr[m] >= x) lo = m + 1; else hi = m; }
            } else {          // only elements > x precede
                while (lo < hi){ int m = (lo + hi) >> 1; if (arr[m] >  x) lo = m + 1; else hi = m; }
            }
            rank += lo;
        }
        g_rank2pos[b*CAND + rank]   = t;
        g_ss[b*CAND + rank]         = x;
        g_lab_ranked[b*CAND + rank] = g_labelv[b*CAND + t];
    }
}

// per (image,class): build class list (warp ballot, rank-ordered) + greedy NMS
__global__ __launch_bounds__(256) void k_nms(){
    const int blk = blockIdx.x, b = blk/NC, c = blk%NC;
    __shared__ short slist[3008];
    __shared__ int scount;
    __shared__ float sx1[SHB], sy1[SHB], sx2[SHB], sy2[SHB];
    __shared__ unsigned char skeep[3008];
    const int tid = threadIdx.x, lane = tid & 31;

    if (tid < 32){
        int basec = 0;
        for (int r0 = 0; r0 < CAND; r0 += 32){
            int r = r0 + lane;
            int lab = (r < CAND) ? g_lab_ranked[b*CAND + r] : -1;
            bool m = (lab == c);
            unsigned bal = __ballot_sync(0xFFFFFFFFu, m);
            if (m) slist[basec + __popc(bal & ((1u << lane) - 1u))] = (short)r;
            basec += __popc(bal);
        }
        if (lane == 0) scount = basec;
    }
    __syncthreads();
    const int cnt = scount;
    if (cnt == 0) return;

    const float off = (float)c * 2049.0f;
    for (int m = tid; m < cnt; m += 256){
        int r = slist[m];
        int pos = g_rank2pos[b*CAND + r];
        float x1 = __fadd_rn(g_boxv[(b*CAND+pos)*4+0], off);
        float y1 = __fadd_rn(g_boxv[(b*CAND+pos)*4+1], off);
        float x2 = __fadd_rn(g_boxv[(b*CAND+pos)*4+2], off);
        float y2 = __fadd_rn(g_boxv[(b*CAND+pos)*4+3], off);
        if (m < SHB){ sx1[m]=x1; sy1[m]=y1; sx2[m]=x2; sy2[m]=y2; }
        skeep[m] = 1;
    }
    __syncthreads();

    for (int i = 0; i < cnt; ++i){
        if (skeep[i]){
            float ix1, iy1, ix2, iy2;
            if (i < SHB){ ix1=sx1[i]; iy1=sy1[i]; ix2=sx2[i]; iy2=sy2[i]; }
            else {
                int pos = g_rank2pos[b*CAND + slist[i]];
                ix1 = __fadd_rn(g_boxv[(b*CAND+pos)*4+0], off);
                iy1 = __fadd_rn(g_boxv[(b*CAND+pos)*4+1], off);
                ix2 = __fadd_rn(g_boxv[(b*CAND+pos)*4+2], off);
                iy2 = __fadd_rn(g_boxv[(b*CAND+pos)*4+3], off);
            }
            float ia = __fmul_rn(__fsub_rn(ix2, ix1), __fsub_rn(iy2, iy1));
            for (int m = i + 1 + tid; m < cnt; m += 256){
                if (!skeep[m]) continue;
                float mx1, my1, mx2, my2;
                if (m < SHB){ mx1=sx1[m]; my1=sy1[m]; mx2=sx2[m]; my2=sy2[m]; }
                else {
                    int pos = g_rank2pos[b*CAND + slist[m]];
                    mx1 = __fadd_rn(g_boxv[(b*CAND+pos)*4+0], off);
                    my1 = __fadd_rn(g_boxv[(b*CAND+pos)*4+1], off);
                    mx2 = __fadd_rn(g_boxv[(b*CAND+pos)*4+2], off);
                    my2 = __fadd_rn(g_boxv[(b*CAND+pos)*4+3], off);
                }
                float xx1 = fmaxf(ix1, mx1), yy1 = fmaxf(iy1, my1);
                float xx2 = fminf(ix2, mx2), yy2 = fminf(iy2, my2);
                float w = fmaxf(__fsub_rn(xx2, xx1), 0.0f);
                float hh = fmaxf(__fsub_rn(yy2, yy1), 0.0f);
                float inter = __fmul_rn(w, hh);
                float ma  = __fmul_rn(__fsub_rn(mx2, mx1), __fsub_rn(my2, my1));
                float uni = __fsub_rn(__fadd_rn(ia, ma), inter);
                if (inter / uni > NMS_T) skeep[m] = 0;
            }
        }
        __syncthreads();
    }
    for (int m = tid; m < cnt; m += 256)
        g_keep[b*CAND + slist[m]] = skeep[m];
}

// per image: emit top-100 kept (rank order), pad with non-kept (rank order, score -1)
__global__ __launch_bounds__(1024) void k_final(float* __restrict__ out){
    const int b = blockIdx.x, tid = threadIdx.x;
    __shared__ int ps[1024];

    int flags[3]; int loc = 0;
    #pragma unroll
    for (int w = 0; w < 3; ++w){
        int r = tid*3 + w;
        int f = 0;
        if (r < CAND)
            f = (g_keep[b*CAND + r] && (g_ss[b*CAND + r] > 0.0f)) ? 1 : 0;
        flags[w] = f; loc += f;
    }
    ps[tid] = loc; __syncthreads();
    for (int o = 1; o < 1024; o <<= 1){
        int t = (tid >= o) ? ps[tid - o] : 0;
        __syncthreads();
        ps[tid] += t;
        __syncthreads();
    }
    const int excl  = ps[tid] - loc;
    const int total = ps[1023];

    int s = excl;
    #pragma unroll
    for (int w = 0; w < 3; ++w){
        int r = tid*3 + w;
        if (r < CAND && flags[w]){
            if (s < DETS){
                int pos = g_rank2pos[b*CAND + r];
                float* ob = out + ((size_t)b*DETS + s)*4;
                ob[0] = g_boxv[(b*CAND+pos)*4+0];
                ob[1] = g_boxv[(b*CAND+pos)*4+1];
                ob[2] = g_boxv[(b*CAND+pos)*4+2];
                ob[3] = g_boxv[(b*CAND+pos)*4+3];
                out[NB*DETS*4 + b*DETS + s]           = g_ss[b*CAND + r];
                out[NB*DETS*4 + NB*DETS + b*DETS + s] = (float)g_labelv[b*CAND+pos];
            }
            s++;
        }
    }
    const int base = (total < DETS) ? total : DETS;
    __syncthreads();

    loc = 0; int pflags[3];
    #pragma unroll
    for (int w = 0; w < 3; ++w){
        int r = tid*3 + w;
        int f = (r < CAND && !flags[w]) ? 1 : 0;
        pflags[w] = f; loc += f;
    }
    ps[tid] = loc; __syncthreads();
    for (int o = 1; o < 1024; o <<= 1){
        int t = (tid >= o) ? ps[tid - o] : 0;
        __syncthreads();
        ps[tid] += t;
        __syncthreads();
    }
    int pexcl = ps[tid] - loc;
    s = base + pexcl;
    #pragma unroll
    for (int w = 0; w < 3; ++w){
        int r = tid*3 + w;
        if (r < CAND && pflags[w]){
            if (s < DETS){
                int pos = g_rank2pos[b*CAND + r];
                float* ob = out + ((size_t)b*DETS + s)*4;
                ob[0] = g_boxv[(b*CAND+pos)*4+0];
                ob[1] = g_boxv[(b*CAND+pos)*4+1];
                ob[2] = g_boxv[(b*CAND+pos)*4+2];
                ob[3] = g_boxv[(b*CAND+pos)*4+3];
                out[NB*DETS*4 + b*DETS + s]           = -1.0f;
                out[NB*DETS*4 + NB*DETS + b*DETS + s] = (float)g_labelv[b*CAND+pos];
            }
            s++;
        }
    }
}

// ---------------- host ----------------
extern "C" void kernel_launch(void* const* d_in, const int* in_sizes, int n_in,
                              void* d_out, int out_size){
    const float *cls[3], *reg[3], *ctr[3], *anc[3];
    if (n_in >= 12 && in_sizes[0] == 2621440 && in_sizes[1] == 131072){
        for (int l = 0; l < 3; ++l){
            cls[l] = (const float*)d_in[4*l + 0];
            reg[l] = (const float*)d_in[4*l + 1];
            ctr[l] = (const float*)d_in[4*l + 2];
            anc[l] = (const float*)d_in[4*l + 3];
        }
    } else if (n_in >= 12 && in_sizes[0] == 16384){
        for (int l = 0; l < 3; ++l){
            anc[l] = (const float*)d_in[0 + l];
            cls[l] = (const float*)d_in[3 + l];
            ctr[l] = (const float*)d_in[6 + l];
            reg[l] = (const float*)d_in[9 + l];
        }
    } else {
        for (int l = 0; l < 3; ++l){
            cls[l] = (const float*)d_in[0 + l];
            reg[l] = (const float*)d_in[3 + l];
            ctr[l] = (const float*)d_in[6 + l];
            anc[l] = (const float*)d_in[9 + l];
        }
    }

    static int attr_done = 0;
    if (!attr_done){
        cudaFuncSetAttribute(k_sortlevel, cudaFuncAttributeMaxDynamicSharedMemorySize, DYNBYTES);
        attr_done = 1;
    }

    k_scores<<<dim3(TOT/2048, NB), 256>>>(cls[0], cls[1], cls[2], ctr[0], ctr[1], ctr[2]);
    k_sortlevel<<<NPAIR, 1024, DYNBYTES>>>(cls[0], cls[1], cls[2], ctr[0], ctr[1], ctr[2],
                                           reg[0], reg[1], reg[2], anc[0], anc[1], anc[2]);
    k_merge<<<NPAIR, 1024>>>();
    k_nms<<<NB*NC, 256>>>();
    k_final<<<NB, 1024>>>((float*)d_out);
}